// round 1
// baseline (speedup 1.0000x reference)
#include <cuda_runtime.h>

// Locally connected 2D:
//   y[n,h,w] = relu( sum_{i,j} x[n,h+i,w+j] * W[h,w,i,j] + b[h,w] )
// N=64, H_IN=W_IN=512, K=9, H_OUT=W_OUT=504.
//
// Strategy: lanes carry the batch index n -> weight loads are warp-uniform
// (broadcast LDS, free smem bandwidth); each thread computes T=12 consecutive
// w-outputs for its n with an x sliding window in registers (each x value
// feeds up to 9 FFMAs). CTA = 8 warps = 4 h-rows x 2 n-halves, tile
// 4h x 12w x 64n. Exact tiling: 504 = 42*12 = 126*4; x rows needed
// h0..h0+11 <= 511, cols w0..w0+19 <= 511 -> no boundary predicates.

#define TW 12          // outputs per thread (w)
#define TH 4           // h rows per CTA
#define XC (TW + 8)    // x cols in tile = 20
#define XR (TH + 8)    // x rows in tile = 12
#define NPAD 65        // n-dim pad for conflict-free transpose
#define WROW 12        // padded weight row (9 taps -> 12 floats, 48B aligned)
#define PIX (TH * TW)  // 48 pixels per CTA

// smem layout (floats):
//   XS: [XR*XC][NPAD]            = 240*65  = 15600
//   WS: [PIX][9*WROW]            = 48*108  =  5184   (base 62400B, 16B aligned)
//   OS: [TH*64][13]              = 256*13  =  3328
#define XS_OFF 0
#define WS_OFF (XR * XC * NPAD)                 // 15600
#define OS_OFF (WS_OFF + PIX * 9 * WROW)        // 20784
#define SMEM_FLOATS (OS_OFF + TH * 64 * 13)     // 24112
#define SMEM_BYTES (SMEM_FLOATS * 4)            // 96448

__global__ __launch_bounds__(256, 2)
void lc2d_kernel(const float* __restrict__ x,
                 const float* __restrict__ wgt,
                 const float* __restrict__ bias,
                 float* __restrict__ out)
{
    extern __shared__ float sm[];
    float* XS = sm + XS_OFF;
    float* WS = sm + WS_OFF;
    float* OS = sm + OS_OFF;

    const int tid  = threadIdx.x;
    const int lane = tid & 31;
    const int warp = tid >> 5;

    const int w0 = blockIdx.x * TW;   // 0..492
    const int h0 = blockIdx.y * TH;   // 0..500

    // ---- stage x tile: x[n, h0+r, w0+c] -> XS[(r*XC+c)*NPAD + n] ----
    // flat index: c fastest (coalesced gmem read); smem stride 65 between
    // consecutive flat indices -> conflict-free STS.
    {
        const float* xb = x + (size_t)h0 * 512 + w0;
        for (int t = tid; t < 64 * XR * XC; t += 256) {
            int n   = t / (XR * XC);
            int rem = t - n * (XR * XC);
            int r   = rem / XC;
            int c   = rem - r * XC;
            XS[(r * XC + c) * NPAD + n] =
                xb[(size_t)n * (512 * 512) + r * 512 + c];
        }
    }

    // ---- stage weights: W[h0+hl, w0+o, i, j] -> WS[(hl*TW+o)*108 + i*12 + j]
    // gmem is contiguous over (o, i, j) within an h row -> coalesced.
    {
        for (int t = tid; t < PIX * 81; t += 256) {
            int pix = t / 81;
            int q   = t - pix * 81;
            int i   = q / 9;
            int j   = q - i * 9;
            int hl  = pix / TW;
            int o   = pix - hl * TW;
            WS[pix * (9 * WROW) + i * WROW + j] =
                wgt[((size_t)(h0 + hl) * 504 + (w0 + o)) * 81 + q];
        }
    }

    __syncthreads();

    // ---- compute: warp = (h_local, n_half); lane = n within half ----
    const int hl = warp >> 1;
    const int nh = warp & 1;
    const int n  = nh * 32 + lane;
    const int h  = h0 + hl;

    float acc[TW];
#pragma unroll
    for (int o = 0; o < TW; o++) acc[o] = 0.0f;

#pragma unroll
    for (int i = 0; i < 9; i++) {
        const int r = hl + i;
        float xw[XC];
        const float* xrow = &XS[(r * XC) * NPAD + n];
#pragma unroll
        for (int c = 0; c < XC; c++) xw[c] = xrow[c * NPAD];

#pragma unroll
        for (int o = 0; o < TW; o++) {
            const float* wp = &WS[(hl * TW + o) * (9 * WROW) + i * WROW];
            const float4 wa = *reinterpret_cast<const float4*>(wp);      // broadcast
            const float4 wb = *reinterpret_cast<const float4*>(wp + 4);  // broadcast
            const float  w8 = wp[8];
            float a = acc[o];
            a = fmaf(xw[o + 0], wa.x, a);
            a = fmaf(xw[o + 1], wa.y, a);
            a = fmaf(xw[o + 2], wa.z, a);
            a = fmaf(xw[o + 3], wa.w, a);
            a = fmaf(xw[o + 4], wb.x, a);
            a = fmaf(xw[o + 5], wb.y, a);
            a = fmaf(xw[o + 6], wb.z, a);
            a = fmaf(xw[o + 7], wb.w, a);
            a = fmaf(xw[o + 8], w8,   a);
            acc[o] = a;
        }
    }

    // ---- bias + relu, stage to OS for coalesced-ish store ----
    {
        const float* bp = bias + (size_t)h * 504 + w0;
        float* os = &OS[(hl * 64 + n) * 13];
#pragma unroll
        for (int o = 0; o < TW; o++) {
            os[o] = fmaxf(acc[o] + __ldg(bp + o), 0.0f);
        }
    }

    __syncthreads();

    // ---- store: thread t -> (hl2, n2); writes 12 contiguous floats (3x f4) ----
    {
        const int hl2 = tid >> 6;
        const int n2  = tid & 63;
        const float* src = &OS[(hl2 * 64 + n2) * 13];
        float* dst = out + ((size_t)n2 * 504 + (h0 + hl2)) * 504 + w0;
        float4 v0 = make_float4(src[0], src[1], src[2],  src[3]);
        float4 v1 = make_float4(src[4], src[5], src[6],  src[7]);
        float4 v2 = make_float4(src[8], src[9], src[10], src[11]);
        reinterpret_cast<float4*>(dst)[0] = v0;
        reinterpret_cast<float4*>(dst)[1] = v1;
        reinterpret_cast<float4*>(dst)[2] = v2;
    }
}

extern "C" void kernel_launch(void* const* d_in, const int* in_sizes, int n_in,
                              void* d_out, int out_size)
{
    const float* x    = (const float*)d_in[0];
    const float* wgt  = (const float*)d_in[1];
    const float* bias = (const float*)d_in[2];
    float* out        = (float*)d_out;

    cudaFuncSetAttribute(lc2d_kernel,
                         cudaFuncAttributeMaxDynamicSharedMemorySize,
                         SMEM_BYTES);

    dim3 grid(504 / TW, 504 / TH);   // 42 x 126 = 5292 CTAs
    lc2d_kernel<<<grid, 256, SMEM_BYTES>>>(x, wgt, bias, out);
}